// round 8
// baseline (speedup 1.0000x reference)
#include <cuda_runtime.h>

// DDK_77644418777653 — per-row recurrence scan, register-prefetch
// double-buffered SMEM staging.
//
// out[:,0] = 1 ; out[:,k] = out[:,k-1] + alpha/out[:,k-1] - beta*in[:,k-1]
// M = 262144 rows, N = 512 cols, fp32, row-major.
//
// Block = 256 rows (thread = row). Columns in 32 tiles of 16. While tile t is
// computed out of smem buffer A, the float4 loads for tile t+1 are already in
// flight into registers (issued before the compute loop; consumed by STS into
// buffer B after the store of tile t). This keeps DRAM reads busy through the
// serial-divide phase without cp.async's 16B smem-alignment constraint, so
// the odd row stride (LDSR=17 -> bank-conflict-free everywhere) is preserved.
// All global traffic is float4-coalesced: exactly 512 MB read + 512 MB write.
//
// fp semantics are bit-exact vs XLA:GPU's lowering (verified rel_err=0.0 in
// R6 — do NOT change):
//   t  = div.rn(a, w)
//   u  = add.rn(w, t)
//   w' = ffma.rn(-b, x, u)

#define ROWS   256
#define TK     16
#define LDSR   17              // 16 + 1 pad, odd stride -> conflict-free
#define NCOLS  512
#define NT     (NCOLS / TK)    // 32 tiles
#define N4     (NCOLS / 4)
#define LD_IT  ((ROWS * TK / 4) / ROWS)   // 4 float4 slots per thread per tile

__global__ __launch_bounds__(ROWS)
void DDK_77644418777653_kernel(const float* __restrict__ in,
                               const float* __restrict__ alpha,
                               const float* __restrict__ beta,
                               float* __restrict__ out) {
    __shared__ float sm[2][ROWS * LDSR];   // 2 x 17408 B = 34816 B

    const int tid  = threadIdx.x;
    const int row0 = blockIdx.x * ROWS;

    const float a = alpha[0];
    const float b = beta[0];

    const float4* in4  = reinterpret_cast<const float4*>(in);
    float4*       out4 = reinterpret_cast<float4*>(out);

    // Per-thread staging slots: idx = it*ROWS + tid, r = idx>>2, c4 = idx&3.
    // Precompute the four (row, slot) pairs this thread services.
    int rr[LD_IT], cc[LD_IT];
    #pragma unroll
    for (int it = 0; it < LD_IT; ++it) {
        int idx = it * ROWS + tid;
        rr[it] = idx >> 2;
        cc[it] = idx & 3;
    }

    // ---- prologue: load tile 0 into regs, stage to buffer 0 ----
    {
        float4 pf[LD_IT];
        #pragma unroll
        for (int it = 0; it < LD_IT; ++it)
            pf[it] = in4[(size_t)(row0 + rr[it]) * N4 + cc[it]];
        #pragma unroll
        for (int it = 0; it < LD_IT; ++it) {
            float* d = &sm[0][rr[it] * LDSR + cc[it] * 4];
            d[0] = pf[it].x; d[1] = pf[it].y; d[2] = pf[it].z; d[3] = pf[it].w;
        }
    }
    __syncthreads();

    float w     = 1.0f;   // recurrence state for this thread's row
    float xprev = 0.0f;   // input value carried across tile boundary
    bool  first = true;   // col 0 of the row is exactly 1

    for (int t = 0; t < NT; ++t) {
        float* cur = sm[t & 1];

        // ---- issue prefetch LDGs for tile t+1 (in flight during compute) ----
        float4 pf[LD_IT];
        const bool have = (t + 1 < NT);
        if (have) {
            const int kc4 = (t + 1) * (TK / 4);
            #pragma unroll
            for (int it = 0; it < LD_IT; ++it)
                pf[it] = in4[(size_t)(row0 + rr[it]) * N4 + kc4 + cc[it]];
        }

        // ---- per-thread serial recurrence over tile t (in-place) ----
        float* mrow = &cur[tid * LDSR];
        #pragma unroll
        for (int i = 0; i < TK; ++i) {
            float x = mrow[i];  // input col t*TK+i (read before overwrite)
            // out col uses input col-1 = xprev. Exact XLA op sequence.
            float u  = __fadd_rn(w, __fdiv_rn(a, w));
            float wn = __fmaf_rn(-b, xprev, u);
            w = first ? 1.0f : wn;
            mrow[i] = w;
            xprev   = x;
            first   = false;     // constant-folds away for i >= 1
        }
        __syncthreads();   // compute writes visible before cross-row staging reads

        // ---- cooperative coalesced store of tile t ----
        {
            const int kc4 = t * (TK / 4);
            #pragma unroll
            for (int it = 0; it < LD_IT; ++it) {
                const float* s = &cur[rr[it] * LDSR + cc[it] * 4];
                out4[(size_t)(row0 + rr[it]) * N4 + kc4 + cc[it]] =
                    make_float4(s[0], s[1], s[2], s[3]);
            }
        }

        // ---- stage prefetched tile t+1 into the other buffer ----
        // (that buffer's last readers — compute/store of tile t-1 — finished
        //  before the sync above)
        if (have) {
            float* nxt = sm[(t + 1) & 1];
            #pragma unroll
            for (int it = 0; it < LD_IT; ++it) {
                float* d = &nxt[rr[it] * LDSR + cc[it] * 4];
                d[0] = pf[it].x; d[1] = pf[it].y;
                d[2] = pf[it].z; d[3] = pf[it].w;
            }
            __syncthreads();   // staging visible for next tile's compute
        }
    }
}

extern "C" void kernel_launch(void* const* d_in, const int* in_sizes, int n_in,
                              void* d_out, int out_size) {
    const float* in    = (const float*)d_in[0];   // [262144, 512] fp32
    const float* alpha = (const float*)d_in[1];   // [1]
    const float* beta  = (const float*)d_in[2];   // [1]
    float*       out   = (float*)d_out;           // [262144, 512] fp32

    const int M = in_sizes[0] / NCOLS;            // 262144
    DDK_77644418777653_kernel<<<M / ROWS, ROWS>>>(in, alpha, beta, out);
}